// round 4
// baseline (speedup 1.0000x reference)
#include <cuda_runtime.h>
#include <math.h>

#define C_DIM 512
#define CF    256      // cond features
#define NH    8
#define DH    64
#define NTOK  4096     // N*H*W = 4*32*32
#define HH    32
#define WWID  32
#define KSZ   7
#define WIN   49
#define EPSF  1e-6f

// ---------------- scratch (static device globals; no allocations) ------------
__device__ float g_s[C_DIM];
__device__ float g_xn[NTOK * C_DIM];          // 8 MB
__device__ float g_qkv[NTOK * 3 * C_DIM];     // 24 MB  (q|k|v each 512 cols)
__device__ float g_o[NTOK * C_DIM];           // 8 MB

// ---------------- s = cond @ norm_w + 1 --------------------------------------
__global__ void nsab_s_kernel(const float* __restrict__ cond,
                              const float* __restrict__ norm_w) {
    int c = blockIdx.x * blockDim.x + threadIdx.x;
    if (c >= C_DIM) return;
    float acc = 1.0f;
#pragma unroll 8
    for (int k = 0; k < CF; k++) acc += cond[k] * norm_w[k * C_DIM + c];
    g_s[c] = acc;
}

// ---------------- RMS norm + layout transpose (B,C,T,H,W) -> (tok, C) --------
__global__ void nsab_rms_kernel(const float* __restrict__ x) {
    int tok = blockIdx.x;
    int tid = threadIdx.x;                 // 256 threads
    int c0 = tid, c1 = tid + 256;
    float v0 = x[c0 * NTOK + tok];
    float v1 = x[c1 * NTOK + tok];
    float ss = v0 * v0 + v1 * v1;
#pragma unroll
    for (int o = 16; o; o >>= 1) ss += __shfl_xor_sync(0xFFFFFFFFu, ss, o);
    __shared__ float red[8];
    if ((tid & 31) == 0) red[tid >> 5] = ss;
    __syncthreads();
    float tot = 0.0f;
#pragma unroll
    for (int i = 0; i < 8; i++) tot += red[i];
    float rinv = rsqrtf(tot * (1.0f / (float)C_DIM) + EPSF);
    g_xn[tok * C_DIM + c0] = v0 * g_s[c0] * rinv;
    g_xn[tok * C_DIM + c1] = v1 * g_s[c1] * rinv;
}

// ---------------- generic 64x64x16 register-tiled SGEMM ----------------------
// EPI==0 : C[r*N + c] = acc                              (qkv projection)
// EPI==1 : C[c*M + r] = acc + skip[c*M + r]              (out proj, fused
//          transpose back to (C, tok) layout + residual add)
template <int EPI>
__global__ void nsab_sgemm(const float* __restrict__ A, const float* __restrict__ B,
                           float* __restrict__ Cmat, const float* __restrict__ skip,
                           int M, int N, int K) {
    __shared__ float As[16][68];   // padded: conflict-light, float4-aligned rows
    __shared__ float Bs[16][68];
    int tid = threadIdx.x;         // 256
    int brow = blockIdx.y * 64;
    int bcol = blockIdx.x * 64;
    int tx = tid & 15, ty = tid >> 4;

    float acc[4][4];
#pragma unroll
    for (int i = 0; i < 4; i++)
#pragma unroll
        for (int j = 0; j < 4; j++) acc[i][j] = 0.0f;

    const float* Aptr = A + (size_t)brow * K;
    const float* Bptr = B + bcol;

    // A-load mapping: thread -> (m = tid>>2, kf = (tid&3)*4), one float4 each
    int am = tid >> 2;
    int akf = (tid & 3) * 4;
    // B-load mapping: thread -> (kk = tid>>4, nn = (tid&15)*4), one float4 each
    int bkk = tid >> 4;
    int bnn = (tid & 15) * 4;

    for (int k0 = 0; k0 < K; k0 += 16) {
        float4 a4 = *(const float4*)&Aptr[(size_t)am * K + k0 + akf];
        As[akf + 0][am] = a4.x;
        As[akf + 1][am] = a4.y;
        As[akf + 2][am] = a4.z;
        As[akf + 3][am] = a4.w;
        float4 b4 = *(const float4*)&Bptr[(size_t)(k0 + bkk) * N + bnn];
        *(float4*)&Bs[bkk][bnn] = b4;
        __syncthreads();
#pragma unroll
        for (int kk = 0; kk < 16; kk++) {
            float4 a = *(const float4*)&As[kk][ty * 4];
            float4 b = *(const float4*)&Bs[kk][tx * 4];
            acc[0][0] += a.x * b.x; acc[0][1] += a.x * b.y; acc[0][2] += a.x * b.z; acc[0][3] += a.x * b.w;
            acc[1][0] += a.y * b.x; acc[1][1] += a.y * b.y; acc[1][2] += a.y * b.z; acc[1][3] += a.y * b.w;
            acc[2][0] += a.z * b.x; acc[2][1] += a.z * b.y; acc[2][2] += a.z * b.z; acc[2][3] += a.z * b.w;
            acc[3][0] += a.w * b.x; acc[3][1] += a.w * b.y; acc[3][2] += a.w * b.z; acc[3][3] += a.w * b.w;
        }
        __syncthreads();
    }

#pragma unroll
    for (int i = 0; i < 4; i++) {
        int r = brow + ty * 4 + i;
#pragma unroll
        for (int j = 0; j < 4; j++) {
            int c = bcol + tx * 4 + j;
            if (EPI == 0) {
                Cmat[(size_t)r * N + c] = acc[i][j];
            } else {
                size_t idx = (size_t)c * M + r;
                Cmat[idx] = acc[i][j] + skip[idx];
            }
        }
    }
}

// ---------------- QK L2-norm + RoPE (in place on g_qkv) ----------------------
__global__ void nsab_rope_kernel(const float* __restrict__ pos,
                                 const float* __restrict__ scale) {
    int b = blockIdx.x;
    int tok = b >> 3, head = b & 7;
    int e = threadIdx.x;               // 64
    int hw = tok & 1023;
    float px = pos[hw * 2 + 0];
    float py = pos[hw * 2 + 1];

    float* qp = &g_qkv[(size_t)tok * 1536 + head * 64 + e];
    float* kp = qp + 512;
    float q = *qp, k = *kp;

    float sq = q * q, sk = k * k;
#pragma unroll
    for (int o = 16; o; o >>= 1) {
        sq += __shfl_xor_sync(0xFFFFFFFFu, sq, o);
        sk += __shfl_xor_sync(0xFFFFFFFFu, sk, o);
    }
    __shared__ float sred[4];
    if ((e & 31) == 0) { sred[(e >> 5) * 2] = sq; sred[(e >> 5) * 2 + 1] = sk; }
    __syncthreads();
    float qss = sred[0] + sred[2];
    float kss = sred[1] + sred[3];

    float ssc = sqrtf(scale[head]);
    q *= ssc * rsqrtf(qss + EPSF);
    k *= ssc * rsqrtf(kss + EPSF);

    __shared__ float shq[64], shk[64];
    shq[e] = q; shk[e] = k;
    __syncthreads();

    float qo = q, ko = k;
    if (e < 32) {
        int i = e & 15;                          // theta component 0..15
        int idx = (i & 7) * 8 + head;            // freqs[head][i&7] = f[(i&7)*8+head]
        // f = exp(log(pi) + idx*log(10)/64), computed in fp32 like numpy
        float freq = expf(1.1447298858494002f + (float)idx * 0.03597789207803891f);
        float th = ((i < 8) ? px : py) * freq;
        float ct = cosf(th), st = sinf(th);
        if (e < 16) {
            qo = shq[e] * ct - shq[e + 16] * st;
            ko = shk[e] * ct - shk[e + 16] * st;
        } else {
            qo = shq[e] * ct + shq[e - 16] * st;
            ko = shk[e] * ct + shk[e - 16] * st;
        }
    }
    *qp = qo;
    *kp = ko;
}

// ---------------- 7x7 neighborhood attention ---------------------------------
// one block = (token, head), 64 threads
__global__ void nsab_attn_kernel() {
    int b = blockIdx.x;
    int tok = b >> 3, head = b & 7;
    int n = tok >> 10;
    int hw = tok & 1023;
    int h = hw >> 5, w = hw & 31;
    int e = threadIdx.x;               // 64

    __shared__ float sq[64];
    __shared__ float sl[WIN];

    sq[e] = g_qkv[(size_t)tok * 1536 + head * 64 + e];
    __syncthreads();

    int h0 = min(max(h - 3, 0), HH - KSZ);
    int w0 = min(max(w - 3, 0), WWID - KSZ);

    if (e < WIN) {
        int kr = e / 7, kc = e % 7;
        int ktok = (n << 10) + (h0 + kr) * 32 + (w0 + kc);
        const float4* kp = (const float4*)&g_qkv[(size_t)ktok * 1536 + 512 + head * 64];
        const float4* qp4 = (const float4*)sq;
        float acc = 0.0f;
#pragma unroll
        for (int i = 0; i < 16; i++) {
            float4 kv = kp[i], qv = qp4[i];
            acc += kv.x * qv.x + kv.y * qv.y + kv.z * qv.z + kv.w * qv.w;
        }
        sl[e] = acc;
    }
    __syncthreads();

    float mx = -1e30f;
#pragma unroll
    for (int j = 0; j < WIN; j++) mx = fmaxf(mx, sl[j]);
    __syncthreads();                  // everyone done reading raw logits
    if (e < WIN) sl[e] = __expf(sl[e] - mx);
    __syncthreads();
    float den = 0.0f;
#pragma unroll
    for (int j = 0; j < WIN; j++) den += sl[j];
    float inv = 1.0f / den;

    float acc = 0.0f;
#pragma unroll
    for (int kr = 0; kr < 7; kr++) {
        int ktokr = (n << 10) + (h0 + kr) * 32 + w0;
#pragma unroll
        for (int kc = 0; kc < 7; kc++) {
            float p = sl[kr * 7 + kc];
            acc += p * g_qkv[(size_t)(ktokr + kc) * 1536 + 1024 + head * 64 + e];
        }
    }
    g_o[(size_t)tok * 512 + head * 64 + e] = acc * inv;
}

// ---------------- launch ------------------------------------------------------
extern "C" void kernel_launch(void* const* d_in, const int* in_sizes, int n_in,
                              void* d_out, int out_size) {
    const float* x      = (const float*)d_in[0];
    const float* pos    = (const float*)d_in[1];
    const float* cond   = (const float*)d_in[2];
    const float* norm_w = (const float*)d_in[3];
    const float* qkv_w  = (const float*)d_in[4];
    const float* scale  = (const float*)d_in[5];
    const float* out_w  = (const float*)d_in[6];
    float* out = (float*)d_out;

    float *p_xn, *p_qkv, *p_o;
    cudaGetSymbolAddress((void**)&p_xn,  g_xn);
    cudaGetSymbolAddress((void**)&p_qkv, g_qkv);
    cudaGetSymbolAddress((void**)&p_o,   g_o);

    nsab_s_kernel<<<2, 256>>>(cond, norm_w);
    nsab_rms_kernel<<<NTOK, 256>>>(x);
    nsab_sgemm<0><<<dim3(3 * C_DIM / 64, NTOK / 64), 256>>>(p_xn, qkv_w, p_qkv, nullptr,
                                                            NTOK, 3 * C_DIM, C_DIM);
    nsab_rope_kernel<<<NTOK * NH, 64>>>(pos, scale);
    nsab_attn_kernel<<<NTOK * NH, 64>>>();
    nsab_sgemm<1><<<dim3(C_DIM / 64, NTOK / 64), 256>>>(p_o, out_w, out, x,
                                                        NTOK, C_DIM, C_DIM);
}

// round 5
// speedup vs baseline: 1.0701x; 1.0701x over previous
#include <cuda_runtime.h>
#include <math.h>
#include <stdint.h>

#define C_DIM 512
#define CF    256      // cond features
#define NH    8
#define DH    64
#define NTOK  4096     // N*H*W = 4*32*32
#define HH    32
#define WWID  32
#define KSZ   7
#define WIN   49
#define EPSF  1e-6f

// ---------------- scratch (static device globals; no allocations) ------------
__device__ float g_s[C_DIM];
__device__ float g_rinv[NTOK];
__device__ float g_xn[NTOK * C_DIM];          // 8 MB
__device__ float g_qkv[NTOK * 3 * C_DIM];     // 24 MB  (q|k|v each 512 cols)
__device__ float g_o[NTOK * C_DIM];           // 8 MB

// ---------------- s = cond @ norm_w + 1 --------------------------------------
__global__ void nsab_s_kernel(const float* __restrict__ cond,
                              const float* __restrict__ norm_w) {
    int c = blockIdx.x * blockDim.x + threadIdx.x;
    if (c >= C_DIM) return;
    float acc = 1.0f;
#pragma unroll 8
    for (int k = 0; k < CF; k++) acc += cond[k] * norm_w[k * C_DIM + c];
    g_s[c] = acc;
}

// ---------------- per-token sum-of-squares (coalesced along tok) -------------
__global__ void nsab_sumsq_kernel(const float* __restrict__ x) {
    int tok = blockIdx.x * 256 + threadIdx.x;
    float ss = 0.0f;
#pragma unroll 16
    for (int c = 0; c < C_DIM; c++) {
        float v = x[c * NTOK + tok];
        ss += v * v;
    }
    g_rinv[tok] = rsqrtf(ss * (1.0f / (float)C_DIM) + EPSF);
}

// ---------------- transpose (C,tok)->(tok,C) + fused norm scaling ------------
__global__ void nsab_norm_tr_kernel(const float* __restrict__ x) {
    __shared__ float t[32][33];
    int c0 = blockIdx.x * 32;
    int tok0 = blockIdx.y * 32;
    int tx = threadIdx.x, ty = threadIdx.y;   // (32, 8)
#pragma unroll
    for (int i = 0; i < 4; i++) {
        int c = ty + 8 * i;
        t[c][tx] = x[(size_t)(c0 + c) * NTOK + tok0 + tx];
    }
    __syncthreads();
#pragma unroll
    for (int i = 0; i < 4; i++) {
        int row = ty + 8 * i;                 // token within tile
        g_xn[(size_t)(tok0 + row) * C_DIM + c0 + tx] =
            t[tx][row] * g_s[c0 + tx] * g_rinv[tok0 + row];
    }
}

// ---------------- tf32 tensor-core GEMM (m16n8k8 mma.sync) -------------------
// BM=128, BN=128, BK=32, 256 threads = 8 warps (2 M-warps x 4 N-warps),
// warp tile 64x32, 4x4 mma tiles of m16n8k8.
// k within each 8-group stored interleaved [0,4,1,5,2,6,3,7] so each lane's
// fragment pair (kk=c, kk=c+4) is one aligned LDS.64. Row stride 40 words
// keeps fragment LDS conflict-free.
// EPI==0 : C[r*N + c] = acc
// EPI==1 : C[c*M + r] = acc + skip[c*M + r]   (transpose-back + residual)
__device__ __forceinline__ uint32_t f2tf32(float v) {
    uint32_t r;
    asm("cvt.rna.tf32.f32 %0, %1;" : "=r"(r) : "f"(v));
    return r;
}

template <int EPI>
__global__ __launch_bounds__(256) void nsab_mma_gemm(
    const float* __restrict__ A, const float* __restrict__ B,
    float* __restrict__ Cmat, const float* __restrict__ skip,
    int M, int N, int K) {
    __shared__ uint32_t As[128 * 40];
    __shared__ uint32_t Bs[128 * 40];

    const int tid = threadIdx.x;
    const int brow = blockIdx.y * 128;
    const int bcol = blockIdx.x * 128;

    const int warp = tid >> 5;
    const int lane = tid & 31;
    const int wm = warp >> 2;           // 0..1
    const int wn = warp & 3;            // 0..3
    const int m_warp = wm * 64;
    const int n_warp = wn * 32;
    const int r = lane >> 2;            // 0..7
    const int c = lane & 3;             // 0..3

    float acc[4][4][4];
#pragma unroll
    for (int mt = 0; mt < 4; mt++)
#pragma unroll
        for (int nt = 0; nt < 4; nt++)
#pragma unroll
            for (int i = 0; i < 4; i++) acc[mt][nt][i] = 0.0f;

    const int KT = K >> 5;              // k-tiles of 32
    float4 pa[4], pb[4];

    // ---- prologue: load tile 0 ----
#pragma unroll
    for (int i = 0; i < 4; i++) {
        int f = tid + 256 * i;
        int row = f >> 3, kq = f & 7;
        pa[i] = *(const float4*)&A[(size_t)(brow + row) * K + 4 * kq];
        int krow = f >> 5, nq = f & 31;
        pb[i] = *(const float4*)&B[(size_t)krow * N + bcol + 4 * nq];
    }
    // STS (with tf32 convert + k-interleave)
#pragma unroll
    for (int i = 0; i < 4; i++) {
        int f = tid + 256 * i;
        int row = f >> 3, kq = f & 7;
        int base = row * 40 + (kq >> 1) * 8 + (kq & 1);
        As[base + 0] = f2tf32(pa[i].x);
        As[base + 2] = f2tf32(pa[i].y);
        As[base + 4] = f2tf32(pa[i].z);
        As[base + 6] = f2tf32(pa[i].w);
        int krow = f >> 5, nq = f & 31;
        int jb = krow & 7;
        int sB = (krow >> 3) * 8 + ((jb & 3) << 1) + (jb >> 2);
        int nb = 4 * nq;
        Bs[(nb + 0) * 40 + sB] = f2tf32(pb[i].x);
        Bs[(nb + 1) * 40 + sB] = f2tf32(pb[i].y);
        Bs[(nb + 2) * 40 + sB] = f2tf32(pb[i].z);
        Bs[(nb + 3) * 40 + sB] = f2tf32(pb[i].w);
    }
    __syncthreads();

    for (int kt = 0; kt < KT; kt++) {
        const bool has_next = (kt + 1 < KT);
        if (has_next) {
            int k0 = (kt + 1) * 32;
#pragma unroll
            for (int i = 0; i < 4; i++) {
                int f = tid + 256 * i;
                int row = f >> 3, kq = f & 7;
                pa[i] = *(const float4*)&A[(size_t)(brow + row) * K + k0 + 4 * kq];
                int krow = f >> 5, nq = f & 31;
                pb[i] = *(const float4*)&B[(size_t)(k0 + krow) * N + bcol + 4 * nq];
            }
        }

        // ---- compute: 4 k-steps of 8 ----
#pragma unroll
        for (int j = 0; j < 4; j++) {
            uint2 afr[4][2];
#pragma unroll
            for (int mt = 0; mt < 4; mt++) {
                int row = m_warp + mt * 16 + r;
                afr[mt][0] = *(const uint2*)&As[row * 40 + j * 8 + 2 * c];
                afr[mt][1] = *(const uint2*)&As[(row + 8) * 40 + j * 8 + 2 * c];
            }
            uint2 bfr[4];
#pragma unroll
            for (int nt = 0; nt < 4; nt++) {
                bfr[nt] = *(const uint2*)&Bs[(n_warp + nt * 8 + r) * 40 + j * 8 + 2 * c];
            }
#pragma unroll
            for (int mt = 0; mt < 4; mt++)
#pragma unroll
                for (int nt = 0; nt < 4; nt++) {
                    asm volatile(
                        "mma.sync.aligned.m16n8k8.row.col.f32.tf32.tf32.f32 "
                        "{%0,%1,%2,%3}, {%4,%5,%6,%7}, {%8,%9}, {%0,%1,%2,%3};"
                        : "+f"(acc[mt][nt][0]), "+f"(acc[mt][nt][1]),
                          "+f"(acc[mt][nt][2]), "+f"(acc[mt][nt][3])
                        : "r"(afr[mt][0].x), "r"(afr[mt][1].x),
                          "r"(afr[mt][0].y), "r"(afr[mt][1].y),
                          "r"(bfr[nt].x), "r"(bfr[nt].y));
                }
        }

        __syncthreads();
        if (has_next) {
#pragma unroll
            for (int i = 0; i < 4; i++) {
                int f = tid + 256 * i;
                int row = f >> 3, kq = f & 7;
                int base = row * 40 + (kq >> 1) * 8 + (kq & 1);
                As[base + 0] = f2tf32(pa[i].x);
                As[base + 2] = f2tf32(pa[i].y);
                As[base + 4] = f2tf32(pa[i].z);
                As[base + 6] = f2tf32(pa[i].w);
                int krow = f >> 5, nq = f & 31;
                int jb = krow & 7;
                int sB = (krow >> 3) * 8 + ((jb & 3) << 1) + (jb >> 2);
                int nb = 4 * nq;
                Bs[(nb + 0) * 40 + sB] = f2tf32(pb[i].x);
                Bs[(nb + 1) * 40 + sB] = f2tf32(pb[i].y);
                Bs[(nb + 2) * 40 + sB] = f2tf32(pb[i].z);
                Bs[(nb + 3) * 40 + sB] = f2tf32(pb[i].w);
            }
            __syncthreads();
        }
    }

    // ---- epilogue ----
#pragma unroll
    for (int mt = 0; mt < 4; mt++) {
        int row = brow + m_warp + mt * 16 + r;
#pragma unroll
        for (int nt = 0; nt < 4; nt++) {
            int col = bcol + n_warp + nt * 8 + 2 * c;
            if (EPI == 0) {
                float2 v0 = make_float2(acc[mt][nt][0], acc[mt][nt][1]);
                float2 v1 = make_float2(acc[mt][nt][2], acc[mt][nt][3]);
                *(float2*)&Cmat[(size_t)row * N + col] = v0;
                *(float2*)&Cmat[(size_t)(row + 8) * N + col] = v1;
            } else {
                size_t i00 = (size_t)col * M + row;
                size_t i01 = (size_t)(col + 1) * M + row;
                Cmat[i00] = acc[mt][nt][0] + skip[i00];
                Cmat[i01] = acc[mt][nt][1] + skip[i01];
                Cmat[i00 + 8] = acc[mt][nt][2] + skip[i00 + 8];
                Cmat[i01 + 8] = acc[mt][nt][3] + skip[i01 + 8];
            }
        }
    }
}

// ---------------- QK L2-norm + RoPE (in place on g_qkv) ----------------------
__global__ void nsab_rope_kernel(const float* __restrict__ pos,
                                 const float* __restrict__ scale) {
    int b = blockIdx.x;
    int tok = b >> 3, head = b & 7;
    int e = threadIdx.x;               // 64
    int hw = tok & 1023;
    float px = pos[hw * 2 + 0];
    float py = pos[hw * 2 + 1];

    float* qp = &g_qkv[(size_t)tok * 1536 + head * 64 + e];
    float* kp = qp + 512;
    float q = *qp, k = *kp;

    float sq = q * q, sk = k * k;
#pragma unroll
    for (int o = 16; o; o >>= 1) {
        sq += __shfl_xor_sync(0xFFFFFFFFu, sq, o);
        sk += __shfl_xor_sync(0xFFFFFFFFu, sk, o);
    }
    __shared__ float sred[4];
    if ((e & 31) == 0) { sred[(e >> 5) * 2] = sq; sred[(e >> 5) * 2 + 1] = sk; }
    __syncthreads();
    float qss = sred[0] + sred[2];
    float kss = sred[1] + sred[3];

    float ssc = sqrtf(scale[head]);
    q *= ssc * rsqrtf(qss + EPSF);
    k *= ssc * rsqrtf(kss + EPSF);

    __shared__ float shq[64], shk[64];
    shq[e] = q; shk[e] = k;
    __syncthreads();

    float qo = q, ko = k;
    if (e < 32) {
        int i = e & 15;                          // theta component 0..15
        int idx = (i & 7) * 8 + head;            // freqs[head][i&7] = f[(i&7)*8+head]
        float freq = expf(1.1447298858494002f + (float)idx * 0.03597789207803891f);
        float th = ((i < 8) ? px : py) * freq;
        float ct = cosf(th), st = sinf(th);
        if (e < 16) {
            qo = shq[e] * ct - shq[e + 16] * st;
            ko = shk[e] * ct - shk[e + 16] * st;
        } else {
            qo = shq[e] * ct + shq[e - 16] * st;
            ko = shk[e] * ct + shk[e - 16] * st;
        }
    }
    *qp = qo;
    *kp = ko;
}

// ---------------- 7x7 neighborhood attention ---------------------------------
__global__ void nsab_attn_kernel() {
    int b = blockIdx.x;
    int tok = b >> 3, head = b & 7;
    int n = tok >> 10;
    int hw = tok & 1023;
    int h = hw >> 5, w = hw & 31;
    int e = threadIdx.x;               // 64

    __shared__ float sq[64];
    __shared__ float sl[WIN];

    sq[e] = g_qkv[(size_t)tok * 1536 + head * 64 + e];
    __syncthreads();

    int h0 = min(max(h - 3, 0), HH - KSZ);
    int w0 = min(max(w - 3, 0), WWID - KSZ);

    if (e < WIN) {
        int kr = e / 7, kc = e % 7;
        int ktok = (n << 10) + (h0 + kr) * 32 + (w0 + kc);
        const float4* kp = (const float4*)&g_qkv[(size_t)ktok * 1536 + 512 + head * 64];
        const float4* qp4 = (const float4*)sq;
        float acc = 0.0f;
#pragma unroll
        for (int i = 0; i < 16; i++) {
            float4 kv = kp[i], qv = qp4[i];
            acc += kv.x * qv.x + kv.y * qv.y + kv.z * qv.z + kv.w * qv.w;
        }
        sl[e] = acc;
    }
    __syncthreads();

    float mx = -1e30f;
#pragma unroll
    for (int j = 0; j < WIN; j++) mx = fmaxf(mx, sl[j]);
    __syncthreads();
    if (e < WIN) sl[e] = __expf(sl[e] - mx);
    __syncthreads();
    float den = 0.0f;
#pragma unroll
    for (int j = 0; j < WIN; j++) den += sl[j];
    float inv = 1.0f / den;

    float acc = 0.0f;
#pragma unroll
    for (int kr = 0; kr < 7; kr++) {
        int ktokr = (n << 10) + (h0 + kr) * 32 + w0;
#pragma unroll
        for (int kc = 0; kc < 7; kc++) {
            float p = sl[kr * 7 + kc];
            acc += p * g_qkv[(size_t)(ktokr + kc) * 1536 + 1024 + head * 64 + e];
        }
    }
    g_o[(size_t)tok * 512 + head * 64 + e] = acc * inv;
}

// ---------------- launch ------------------------------------------------------
extern "C" void kernel_launch(void* const* d_in, const int* in_sizes, int n_in,
                              void* d_out, int out_size) {
    const float* x      = (const float*)d_in[0];
    const float* pos    = (const float*)d_in[1];
    const float* cond   = (const float*)d_in[2];
    const float* norm_w = (const float*)d_in[3];
    const float* qkv_w  = (const float*)d_in[4];
    const float* scale  = (const float*)d_in[5];
    const float* out_w  = (const float*)d_in[6];
    float* out = (float*)d_out;

    float *p_xn, *p_qkv, *p_o;
    cudaGetSymbolAddress((void**)&p_xn,  g_xn);
    cudaGetSymbolAddress((void**)&p_qkv, g_qkv);
    cudaGetSymbolAddress((void**)&p_o,   g_o);

    nsab_s_kernel<<<2, 256>>>(cond, norm_w);
    nsab_sumsq_kernel<<<NTOK / 256, 256>>>(x);
    nsab_norm_tr_kernel<<<dim3(C_DIM / 32, NTOK / 32), dim3(32, 8)>>>(x);
    nsab_mma_gemm<0><<<dim3(3 * C_DIM / 128, NTOK / 128), 256>>>(
        p_xn, qkv_w, p_qkv, nullptr, NTOK, 3 * C_DIM, C_DIM);
    nsab_rope_kernel<<<NTOK * NH, 64>>>(pos, scale);
    nsab_attn_kernel<<<NTOK * NH, 64>>>();
    nsab_mma_gemm<1><<<dim3(C_DIM / 128, NTOK / 128), 256>>>(
        p_o, out_w, out, x, NTOK, C_DIM, C_DIM);
}

// round 7
// speedup vs baseline: 1.7443x; 1.6300x over previous
#include <cuda_runtime.h>
#include <math.h>
#include <stdint.h>

#define C_DIM 512
#define CF    256      // cond features
#define NH    8
#define DH    64
#define NTOK  4096     // N*H*W = 4*32*32
#define HH    32
#define WWID  32
#define KSZ   7
#define WIN   49
#define EPSF  1e-6f

// GEMM tiling
#define BK        32
#define AP        36            // A smem row stride (words): bank = 4r+c, conflict-free
#define BP        136           // B smem k-row stride (words): bank = 8c+r, conflict-free
#define A_WORDS   (128 * AP)    // 4608
#define B_WORDS   (BK * BP)     // 4352
#define STG_WORDS (A_WORDS + B_WORDS)
#define NSTAGE    3
#define GEMM_SMEM (NSTAGE * STG_WORDS * 4)   // 107520 bytes

// ---------------- scratch (static device globals; no allocations) ------------
__device__ float g_s[C_DIM];
__device__ float g_rinv[NTOK];
__device__ float g_xn[NTOK * C_DIM];          // 8 MB
__device__ float g_qkv[NTOK * 3 * C_DIM];     // 24 MB  (q|k|v each 512 cols)
__device__ float g_o[NTOK * C_DIM];           // 8 MB

// ---------------- s = cond @ norm_w + 1 --------------------------------------
__global__ void nsab_s_kernel(const float* __restrict__ cond,
                              const float* __restrict__ norm_w) {
    int c = blockIdx.x * blockDim.x + threadIdx.x;
    if (c >= C_DIM) return;
    float acc = 1.0f;
#pragma unroll 8
    for (int k = 0; k < CF; k++) acc += cond[k] * norm_w[k * C_DIM + c];
    g_s[c] = acc;
}

// ---------------- per-token sum-of-squares (coalesced along tok) -------------
__global__ void nsab_sumsq_kernel(const float* __restrict__ x) {
    int tok = blockIdx.x * 256 + threadIdx.x;
    float ss = 0.0f;
#pragma unroll 16
    for (int c = 0; c < C_DIM; c++) {
        float v = x[c * NTOK + tok];
        ss += v * v;
    }
    g_rinv[tok] = rsqrtf(ss * (1.0f / (float)C_DIM) + EPSF);
}

// ---------------- transpose (C,tok)->(tok,C) + fused norm scaling ------------
__global__ void nsab_norm_tr_kernel(const float* __restrict__ x) {
    __shared__ float t[32][33];
    int c0 = blockIdx.x * 32;
    int tok0 = blockIdx.y * 32;
    int tx = threadIdx.x, ty = threadIdx.y;   // (32, 8)
#pragma unroll
    for (int i = 0; i < 4; i++) {
        int c = ty + 8 * i;
        t[c][tx] = x[(size_t)(c0 + c) * NTOK + tok0 + tx];
    }
    __syncthreads();
#pragma unroll
    for (int i = 0; i < 4; i++) {
        int row = ty + 8 * i;                 // token within tile
        g_xn[(size_t)(tok0 + row) * C_DIM + c0 + tx] =
            t[tx][row] * g_s[c0 + tx] * g_rinv[tok0 + row];
    }
}

// ---------------- tf32 tensor-core GEMM, cp.async 3-stage pipeline -----------
// BM=128, BN=128, BK=32, 256 threads = 8 warps (2x4), warp tile 64x32,
// 4x4 mma m16n8k8 tiles. Raw fp32 bits fed to tf32 mma (HW truncates low 13b).
// EPI==0 : C[r*N + c] = acc
// EPI==1 : C[c*M + r] = acc + skip[c*M + r]   (transpose-back + residual)
__device__ __forceinline__ void cp16(uint32_t dst, const void* src) {
    asm volatile("cp.async.ca.shared.global [%0], [%1], 16;\n"
                 :: "r"(dst), "l"(src));
}
__device__ __forceinline__ void cp_commit() {
    asm volatile("cp.async.commit_group;\n" ::: "memory");
}
__device__ __forceinline__ void cp_wait1() {
    asm volatile("cp.async.wait_group 1;\n" ::: "memory");
}

template <int EPI>
__global__ __launch_bounds__(256, 2) void nsab_mma_gemm(
    const float* __restrict__ A, const float* __restrict__ B,
    float* __restrict__ Cmat, const float* __restrict__ skip,
    int M, int N, int K) {
    extern __shared__ uint32_t sm[];

    const int tid = threadIdx.x;
    const int brow = blockIdx.y * 128;
    const int bcol = blockIdx.x * 128;

    const int warp = tid >> 5;
    const int lane = tid & 31;
    const int m_warp = (warp >> 2) * 64;
    const int n_warp = (warp & 3) * 32;
    const int r = lane >> 2;            // 0..7
    const int c = lane & 3;             // 0..3

    // cp.async source/dest mapping (per thread, 4 chunks each for A and B)
    const int a_row = tid >> 3, a_q = tid & 7;     // +32 rows per iter
    const int b_k = tid >> 5, b_q = tid & 31;      // +8 k-rows per iter
    uint32_t smem_base;
    {
        void* p = (void*)sm;
        smem_base = (uint32_t)__cvta_generic_to_shared(p);
    }

    float acc[4][4][4];
#pragma unroll
    for (int mt = 0; mt < 4; mt++)
#pragma unroll
        for (int nt = 0; nt < 4; nt++)
#pragma unroll
            for (int i = 0; i < 4; i++) acc[mt][nt][i] = 0.0f;

    const int KT = K >> 5;

    // ---- issue a tile's loads into stage s ----
    auto issue = [&](int kt, int s) {
        uint32_t sA = smem_base + (uint32_t)(s * STG_WORDS) * 4u;
        uint32_t sB = sA + A_WORDS * 4u;
#pragma unroll
        for (int i = 0; i < 4; i++) {
            int row = a_row + 32 * i;
            cp16(sA + (uint32_t)(row * AP + a_q * 4) * 4u,
                 A + (size_t)(brow + row) * K + kt * BK + a_q * 4);
        }
#pragma unroll
        for (int i = 0; i < 4; i++) {
            int k = b_k + 8 * i;
            cp16(sB + (uint32_t)(k * BP + b_q * 4) * 4u,
                 B + (size_t)(kt * BK + k) * N + bcol + b_q * 4);
        }
        cp_commit();
    };

    issue(0, 0);
    if (KT > 1) issue(1, 1);

    int stage = 0;
    for (int kt = 0; kt < KT; kt++) {
        cp_wait1();
        __syncthreads();
        if (kt + 2 < KT) {
            int ns = stage + 2; if (ns >= NSTAGE) ns -= NSTAGE;
            issue(kt + 2, ns);
        }

        const uint32_t* Asu = sm + stage * STG_WORDS;
        const uint32_t* Bsu = Asu + A_WORDS;

#pragma unroll
        for (int j = 0; j < 4; j++) {
            uint32_t a[4][4];
#pragma unroll
            for (int mt = 0; mt < 4; mt++) {
                const uint32_t* p0 = Asu + (m_warp + mt * 16 + r) * AP + j * 8 + c;
                a[mt][0] = p0[0];
                a[mt][2] = p0[4];
                a[mt][1] = p0[8 * AP];
                a[mt][3] = p0[8 * AP + 4];
            }
            uint32_t b0[4], b1[4];
#pragma unroll
            for (int nt = 0; nt < 4; nt++) {
                const uint32_t* q0 = Bsu + (j * 8 + c) * BP + n_warp + nt * 8 + r;
                b0[nt] = q0[0];
                b1[nt] = q0[4 * BP];
            }
#pragma unroll
            for (int mt = 0; mt < 4; mt++)
#pragma unroll
                for (int nt = 0; nt < 4; nt++) {
                    asm volatile(
                        "mma.sync.aligned.m16n8k8.row.col.f32.tf32.tf32.f32 "
                        "{%0,%1,%2,%3}, {%4,%5,%6,%7}, {%8,%9}, {%0,%1,%2,%3};"
                        : "+f"(acc[mt][nt][0]), "+f"(acc[mt][nt][1]),
                          "+f"(acc[mt][nt][2]), "+f"(acc[mt][nt][3])
                        : "r"(a[mt][0]), "r"(a[mt][1]),
                          "r"(a[mt][2]), "r"(a[mt][3]),
                          "r"(b0[nt]), "r"(b1[nt]));
                }
        }

        stage++; if (stage >= NSTAGE) stage -= NSTAGE;
        __syncthreads();
    }

    // ---- epilogue ----
#pragma unroll
    for (int mt = 0; mt < 4; mt++) {
        int row = brow + m_warp + mt * 16 + r;
#pragma unroll
        for (int nt = 0; nt < 4; nt++) {
            int col = bcol + n_warp + nt * 8 + 2 * c;
            if (EPI == 0) {
                float2 v0 = make_float2(acc[mt][nt][0], acc[mt][nt][1]);
                float2 v1 = make_float2(acc[mt][nt][2], acc[mt][nt][3]);
                *(float2*)&Cmat[(size_t)row * N + col] = v0;
                *(float2*)&Cmat[(size_t)(row + 8) * N + col] = v1;
            } else {
                size_t i00 = (size_t)col * M + row;
                size_t i01 = (size_t)(col + 1) * M + row;
                Cmat[i00] = acc[mt][nt][0] + skip[i00];
                Cmat[i01] = acc[mt][nt][1] + skip[i01];
                Cmat[i00 + 8] = acc[mt][nt][2] + skip[i00 + 8];
                Cmat[i01 + 8] = acc[mt][nt][3] + skip[i01 + 8];
            }
        }
    }
}

// ---------------- QK L2-norm + RoPE (in place on g_qkv) ----------------------
__global__ void nsab_rope_kernel(const float* __restrict__ pos,
                                 const float* __restrict__ scale) {
    int b = blockIdx.x;
    int tok = b >> 3, head = b & 7;
    int e = threadIdx.x;               // 64
    int hw = tok & 1023;
    float px = pos[hw * 2 + 0];
    float py = pos[hw * 2 + 1];

    float* qp = &g_qkv[(size_t)tok * 1536 + head * 64 + e];
    float* kp = qp + 512;
    float q = *qp, k = *kp;

    float sq = q * q, sk = k * k;
#pragma unroll
    for (int o = 16; o; o >>= 1) {
        sq += __shfl_xor_sync(0xFFFFFFFFu, sq, o);
        sk += __shfl_xor_sync(0xFFFFFFFFu, sk, o);
    }
    __shared__ float sred[4];
    if ((e & 31) == 0) { sred[(e >> 5) * 2] = sq; sred[(e >> 5) * 2 + 1] = sk; }
    __syncthreads();
    float qss = sred[0] + sred[2];
    float kss = sred[1] + sred[3];

    float ssc = sqrtf(scale[head]);
    q *= ssc * rsqrtf(qss + EPSF);
    k *= ssc * rsqrtf(kss + EPSF);

    __shared__ float shq[64], shk[64];
    shq[e] = q; shk[e] = k;
    __syncthreads();

    float qo = q, ko = k;
    if (e < 32) {
        int i = e & 15;                          // theta component 0..15
        int idx = (i & 7) * 8 + head;            // freqs[head][i&7] = f[(i&7)*8+head]
        float freq = expf(1.1447298858494002f + (float)idx * 0.03597789207803891f);
        float th = ((i < 8) ? px : py) * freq;
        float ct = cosf(th), st = sinf(th);
        if (e < 16) {
            qo = shq[e] * ct - shq[e + 16] * st;
            ko = shk[e] * ct - shk[e + 16] * st;
        } else {
            qo = shq[e] * ct + shq[e - 16] * st;
            ko = shk[e] * ct + shk[e - 16] * st;
        }
    }
    *qp = qo;
    *kp = ko;
}

// ---------------- 7x7 neighborhood attention ---------------------------------
__global__ void nsab_attn_kernel() {
    int b = blockIdx.x;
    int tok = b >> 3, head = b & 7;
    int n = tok >> 10;
    int hw = tok & 1023;
    int h = hw >> 5, w = hw & 31;
    int e = threadIdx.x;               // 64

    __shared__ float sq[64];
    __shared__ float sl[WIN];

    sq[e] = g_qkv[(size_t)tok * 1536 + head * 64 + e];
    __syncthreads();

    int h0 = min(max(h - 3, 0), HH - KSZ);
    int w0 = min(max(w - 3, 0), WWID - KSZ);

    if (e < WIN) {
        int kr = e / 7, kc = e % 7;
        int ktok = (n << 10) + (h0 + kr) * 32 + (w0 + kc);
        const float4* kp = (const float4*)&g_qkv[(size_t)ktok * 1536 + 512 + head * 64];
        const float4* qp4 = (const float4*)sq;
        float acc = 0.0f;
#pragma unroll
        for (int i = 0; i < 16; i++) {
            float4 kv = kp[i], qv = qp4[i];
            acc += kv.x * qv.x + kv.y * qv.y + kv.z * qv.z + kv.w * qv.w;
        }
        sl[e] = acc;
    }
    __syncthreads();

    float mx = -1e30f;
#pragma unroll
    for (int j = 0; j < WIN; j++) mx = fmaxf(mx, sl[j]);
    __syncthreads();
    if (e < WIN) sl[e] = __expf(sl[e] - mx);
    __syncthreads();
    float den = 0.0f;
#pragma unroll
    for (int j = 0; j < WIN; j++) den += sl[j];
    float inv = 1.0f / den;

    float acc = 0.0f;
#pragma unroll
    for (int kr = 0; kr < 7; kr++) {
        int ktokr = (n << 10) + (h0 + kr) * 32 + w0;
#pragma unroll
        for (int kc = 0; kc < 7; kc++) {
            float p = sl[kr * 7 + kc];
            acc += p * g_qkv[(size_t)(ktokr + kc) * 1536 + 1024 + head * 64 + e];
        }
    }
    g_o[(size_t)tok * 512 + head * 64 + e] = acc * inv;
}

// ---------------- launch ------------------------------------------------------
extern "C" void kernel_launch(void* const* d_in, const int* in_sizes, int n_in,
                              void* d_out, int out_size) {
    const float* x      = (const float*)d_in[0];
    const float* pos    = (const float*)d_in[1];
    const float* cond   = (const float*)d_in[2];
    const float* norm_w = (const float*)d_in[3];
    const float* qkv_w  = (const float*)d_in[4];
    const float* scale  = (const float*)d_in[5];
    const float* out_w  = (const float*)d_in[6];
    float* out = (float*)d_out;

    float *p_xn, *p_qkv, *p_o;
    cudaGetSymbolAddress((void**)&p_xn,  g_xn);
    cudaGetSymbolAddress((void**)&p_qkv, g_qkv);
    cudaGetSymbolAddress((void**)&p_o,   g_o);

    cudaFuncSetAttribute(nsab_mma_gemm<0>,
                         cudaFuncAttributeMaxDynamicSharedMemorySize, GEMM_SMEM);
    cudaFuncSetAttribute(nsab_mma_gemm<1>,
                         cudaFuncAttributeMaxDynamicSharedMemorySize, GEMM_SMEM);

    nsab_s_kernel<<<2, 256>>>(cond, norm_w);
    nsab_sumsq_kernel<<<NTOK / 256, 256>>>(x);
    nsab_norm_tr_kernel<<<dim3(C_DIM / 32, NTOK / 32), dim3(32, 8)>>>(x);
    nsab_mma_gemm<0><<<dim3(3 * C_DIM / 128, NTOK / 128), 256, GEMM_SMEM>>>(
        p_xn, qkv_w, p_qkv, nullptr, NTOK, 3 * C_DIM, C_DIM);
    nsab_rope_kernel<<<NTOK * NH, 64>>>(pos, scale);
    nsab_attn_kernel<<<NTOK * NH, 64>>>();
    nsab_mma_gemm<1><<<dim3(C_DIM / 128, NTOK / 128), 256, GEMM_SMEM>>>(
        p_o, out_w, out, x, NTOK, C_DIM, C_DIM);
}

// round 8
// speedup vs baseline: 2.7750x; 1.5909x over previous
#include <cuda_runtime.h>
#include <math.h>
#include <stdint.h>

#define C_DIM 512
#define CF    256      // cond features
#define NH    8
#define DH    64
#define NTOK  4096     // N*H*W = 4*32*32
#define HH    32
#define WWID  32
#define KSZ   7
#define WIN   49
#define EPSF  1e-6f

// GEMM tiling
#define BK        32
#define AP        36            // A smem row stride (words): bank = 4r+c, conflict-free
#define BP        136           // B smem k-row stride (words): bank = 8c+r, conflict-free
#define A_WORDS   (128 * AP)    // 4608
#define B_WORDS   (BK * BP)     // 4352
#define STG_WORDS (A_WORDS + B_WORDS)
#define NSTAGE    3
#define GEMM_SMEM (NSTAGE * STG_WORDS * 4)   // 107520 bytes

// attention tiling: 4x4 token tile, window union <= 10x10
#define ATILE     4
#define SPAN      10
#define KVSTRIDE  68            // padded row stride (words) for K/V smem rows
#define ATTN_SMEM ((SPAN * SPAN * KVSTRIDE * 2 + 16 * KVSTRIDE + 16 * 52 + 16) * 4)

// fused norm smem: x tile [512][33] + reductions
#define NORM_SMEM ((C_DIM * 33 + 8 * 33 + 32) * 4)

// ---------------- scratch (static device globals; no allocations) ------------
__device__ float g_s[C_DIM];
__device__ float g_xn[NTOK * C_DIM];          // 8 MB
__device__ float g_qkv[NTOK * 3 * C_DIM];     // 24 MB  (q|k|v each 512 cols)
__device__ float g_o[NTOK * C_DIM];           // 8 MB

// ---------------- s = cond @ norm_w + 1 --------------------------------------
__global__ void nsab_s_kernel(const float* __restrict__ cond,
                              const float* __restrict__ norm_w) {
    int c = blockIdx.x * blockDim.x + threadIdx.x;
    if (c >= C_DIM) return;
    float acc = 1.0f;
#pragma unroll 8
    for (int k = 0; k < CF; k++) acc += cond[k] * norm_w[k * C_DIM + c];
    g_s[c] = acc;
}

// ---------------- fused RMS-norm + transpose (C,tok)->(tok,C) ----------------
// one block = 32 tokens; x tile staged in smem, sum-sq reduced in-block.
__global__ __launch_bounds__(256) void nsab_norm_fused(const float* __restrict__ x) {
    extern __shared__ float smf[];
    float* t    = smf;                       // [512][33]
    float* red  = smf + C_DIM * 33;          // [8][33]
    float* rsh  = red + 8 * 33;              // [32]

    int tok0 = blockIdx.x * 32;
    int tx = threadIdx.x & 31;               // token lane
    int ty = threadIdx.x >> 5;               // 0..7

    float ss = 0.0f;
#pragma unroll 16
    for (int i = 0; i < 64; i++) {
        int c = ty + 8 * i;
        float v = x[(size_t)c * NTOK + tok0 + tx];
        t[c * 33 + tx] = v;
        ss += v * v;
    }
    red[ty * 33 + tx] = ss;
    __syncthreads();
    if (ty == 0) {
        float tot = 0.0f;
#pragma unroll
        for (int j = 0; j < 8; j++) tot += red[j * 33 + tx];
        rsh[tx] = rsqrtf(tot * (1.0f / (float)C_DIM) + EPSF);
    }
    __syncthreads();

    // write transposed + scaled: thread tx = c lane, cover 16 c-blocks x 4 rows
#pragma unroll 4
    for (int cc = 0; cc < 16; cc++) {
        int c = cc * 32 + tx;
        float sc = g_s[c];
#pragma unroll
        for (int rr = 0; rr < 4; rr++) {
            int row = ty * 4 + rr;
            g_xn[(size_t)(tok0 + row) * C_DIM + c] = t[c * 33 + row] * sc * rsh[row];
        }
    }
}

// ---------------- tf32 tensor-core GEMM, cp.async 3-stage pipeline -----------
__device__ __forceinline__ void cp16(uint32_t dst, const void* src) {
    asm volatile("cp.async.ca.shared.global [%0], [%1], 16;\n"
                 :: "r"(dst), "l"(src));
}
__device__ __forceinline__ void cp_commit() {
    asm volatile("cp.async.commit_group;\n" ::: "memory");
}
__device__ __forceinline__ void cp_wait1() {
    asm volatile("cp.async.wait_group 1;\n" ::: "memory");
}

template <int EPI>
__global__ __launch_bounds__(256, 2) void nsab_mma_gemm(
    const float* __restrict__ A, const float* __restrict__ B,
    float* __restrict__ Cmat, const float* __restrict__ skip,
    int M, int N, int K) {
    extern __shared__ uint32_t sm[];

    const int tid = threadIdx.x;
    const int brow = blockIdx.y * 128;
    const int bcol = blockIdx.x * 128;

    const int warp = tid >> 5;
    const int lane = tid & 31;
    const int m_warp = (warp >> 2) * 64;
    const int n_warp = (warp & 3) * 32;
    const int r = lane >> 2;            // 0..7
    const int c = lane & 3;             // 0..3

    const int a_row = tid >> 3, a_q = tid & 7;
    const int b_k = tid >> 5, b_q = tid & 31;
    uint32_t smem_base;
    {
        void* p = (void*)sm;
        smem_base = (uint32_t)__cvta_generic_to_shared(p);
    }

    float acc[4][4][4];
#pragma unroll
    for (int mt = 0; mt < 4; mt++)
#pragma unroll
        for (int nt = 0; nt < 4; nt++)
#pragma unroll
            for (int i = 0; i < 4; i++) acc[mt][nt][i] = 0.0f;

    const int KT = K >> 5;

    auto issue = [&](int kt, int s) {
        uint32_t sA = smem_base + (uint32_t)(s * STG_WORDS) * 4u;
        uint32_t sB = sA + A_WORDS * 4u;
#pragma unroll
        for (int i = 0; i < 4; i++) {
            int row = a_row + 32 * i;
            cp16(sA + (uint32_t)(row * AP + a_q * 4) * 4u,
                 A + (size_t)(brow + row) * K + kt * BK + a_q * 4);
        }
#pragma unroll
        for (int i = 0; i < 4; i++) {
            int k = b_k + 8 * i;
            cp16(sB + (uint32_t)(k * BP + b_q * 4) * 4u,
                 B + (size_t)(kt * BK + k) * N + bcol + b_q * 4);
        }
        cp_commit();
    };

    issue(0, 0);
    if (KT > 1) issue(1, 1);

    int stage = 0;
    for (int kt = 0; kt < KT; kt++) {
        cp_wait1();
        __syncthreads();
        if (kt + 2 < KT) {
            int ns = stage + 2; if (ns >= NSTAGE) ns -= NSTAGE;
            issue(kt + 2, ns);
        }

        const uint32_t* Asu = sm + stage * STG_WORDS;
        const uint32_t* Bsu = Asu + A_WORDS;

#pragma unroll
        for (int j = 0; j < 4; j++) {
            uint32_t a[4][4];
#pragma unroll
            for (int mt = 0; mt < 4; mt++) {
                const uint32_t* p0 = Asu + (m_warp + mt * 16 + r) * AP + j * 8 + c;
                a[mt][0] = p0[0];
                a[mt][2] = p0[4];
                a[mt][1] = p0[8 * AP];
                a[mt][3] = p0[8 * AP + 4];
            }
            uint32_t b0[4], b1[4];
#pragma unroll
            for (int nt = 0; nt < 4; nt++) {
                const uint32_t* q0 = Bsu + (j * 8 + c) * BP + n_warp + nt * 8 + r;
                b0[nt] = q0[0];
                b1[nt] = q0[4 * BP];
            }
#pragma unroll
            for (int mt = 0; mt < 4; mt++)
#pragma unroll
                for (int nt = 0; nt < 4; nt++) {
                    asm volatile(
                        "mma.sync.aligned.m16n8k8.row.col.f32.tf32.tf32.f32 "
                        "{%0,%1,%2,%3}, {%4,%5,%6,%7}, {%8,%9}, {%0,%1,%2,%3};"
                        : "+f"(acc[mt][nt][0]), "+f"(acc[mt][nt][1]),
                          "+f"(acc[mt][nt][2]), "+f"(acc[mt][nt][3])
                        : "r"(a[mt][0]), "r"(a[mt][1]),
                          "r"(a[mt][2]), "r"(a[mt][3]),
                          "r"(b0[nt]), "r"(b1[nt]));
                }
        }

        stage++; if (stage >= NSTAGE) stage -= NSTAGE;
        __syncthreads();
    }

#pragma unroll
    for (int mt = 0; mt < 4; mt++) {
        int row = brow + m_warp + mt * 16 + r;
#pragma unroll
        for (int nt = 0; nt < 4; nt++) {
            int col = bcol + n_warp + nt * 8 + 2 * c;
            if (EPI == 0) {
                float2 v0 = make_float2(acc[mt][nt][0], acc[mt][nt][1]);
                float2 v1 = make_float2(acc[mt][nt][2], acc[mt][nt][3]);
                *(float2*)&Cmat[(size_t)row * N + col] = v0;
                *(float2*)&Cmat[(size_t)(row + 8) * N + col] = v1;
            } else {
                size_t i00 = (size_t)col * M + row;
                size_t i01 = (size_t)(col + 1) * M + row;
                Cmat[i00] = acc[mt][nt][0] + skip[i00];
                Cmat[i01] = acc[mt][nt][1] + skip[i01];
                Cmat[i00 + 8] = acc[mt][nt][2] + skip[i00 + 8];
                Cmat[i01 + 8] = acc[mt][nt][3] + skip[i01 + 8];
            }
        }
    }
}

// ---------------- QK L2-norm + RoPE: one block per token, shuffle-only -------
__global__ __launch_bounds__(256) void nsab_rope_kernel(
    const float* __restrict__ pos, const float* __restrict__ scale) {
    int tok = blockIdx.x;
    int head = threadIdx.x >> 5;
    int lane = threadIdx.x & 31;
    int hw = tok & 1023;
    float px = pos[hw * 2 + 0];
    float py = pos[hw * 2 + 1];

    float* qp = &g_qkv[(size_t)tok * 1536 + head * 64 + lane];
    float* kp = qp + 512;
    float q0 = qp[0], q1 = qp[32];
    float k0 = kp[0], k1 = kp[32];

    float sq = q0 * q0 + q1 * q1;
    float sk = k0 * k0 + k1 * k1;
#pragma unroll
    for (int o = 16; o; o >>= 1) {
        sq += __shfl_xor_sync(0xFFFFFFFFu, sq, o);
        sk += __shfl_xor_sync(0xFFFFFFFFu, sk, o);
    }
    float ssc = sqrtf(scale[head]);
    float qn = ssc * rsqrtf(sq + EPSF);
    float kn = ssc * rsqrtf(sk + EPSF);
    q0 *= qn; q1 *= qn;
    k0 *= kn; k1 *= kn;

    // theta identical for lane and lane^16 (depends on lane&15 only)
    int i = lane & 15;
    int idx = (i & 7) * 8 + head;
    float freq = expf(1.1447298858494002f + (float)idx * 0.03597789207803891f);
    float th = ((i < 8) ? px : py) * freq;
    float ct = cosf(th), st = sinf(th);

    float qpart = __shfl_xor_sync(0xFFFFFFFFu, q0, 16);
    float kpart = __shfl_xor_sync(0xFFFFFFFFu, k0, 16);
    float qo, ko;
    if (lane < 16) { qo = q0 * ct - qpart * st; ko = k0 * ct - kpart * st; }
    else           { qo = q0 * ct + qpart * st; ko = k0 * ct + kpart * st; }

    qp[0] = qo;  qp[32] = q1;
    kp[0] = ko;  kp[32] = k1;
}

// ---------------- tiled 7x7 neighborhood attention ---------------------------
// one block = 4x4 token tile x (n, head); K/V window union (<=10x10) in smem.
__global__ __launch_bounds__(256) void nsab_attn_kernel() {
    extern __shared__ float sma[];
    float* sk = sma;                                   // [100][KVSTRIDE]
    float* sv = sk + SPAN * SPAN * KVSTRIDE;           // [100][KVSTRIDE]
    float* sq = sv + SPAN * SPAN * KVSTRIDE;           // [16][KVSTRIDE]
    float* sl = sq + 16 * KVSTRIDE;                    // [16][52]
    float* pinv = sl + 16 * 52;                        // [16]

    int tid = threadIdx.x;
    int th = blockIdx.x >> 3, tw = blockIdx.x & 7;
    int head = blockIdx.y;
    int n = blockIdx.z;
    int h1 = th * ATILE, w1 = tw * ATILE;

    int h0min = min(max(h1 - 3, 0), HH - KSZ);
    int w0min = min(max(w1 - 3, 0), WWID - KSZ);
    int h0max = min(max(h1 + ATILE - 1 - 3, 0), HH - KSZ);
    int w0max = min(max(w1 + ATILE - 1 - 3, 0), WWID - KSZ);
    int span_h = h0max - h0min + KSZ;    // <= 10
    int span_w = w0max - w0min + KSZ;    // <= 10

    // ---- stage K, V window union ----
    int total = span_h * span_w * 16;    // float4 chunks per matrix
    for (int idxi = tid; idxi < total; idxi += 256) {
        int kpos = idxi >> 4, f = idxi & 15;
        int kr = kpos / span_w, kc = kpos - kr * span_w;
        size_t gbase = (size_t)((n << 10) + (h0min + kr) * 32 + (w0min + kc)) * 1536
                       + head * 64 + f * 4;
        float4 kvv = *(const float4*)&g_qkv[gbase + 512];
        float4 vvv = *(const float4*)&g_qkv[gbase + 1024];
        *(float4*)&sk[kpos * KVSTRIDE + f * 4] = kvv;
        *(float4*)&sv[kpos * KVSTRIDE + f * 4] = vvv;
    }
    // ---- stage q for 16 tokens ----
    {
        int tl = tid >> 4, f = tid & 15;
        int hh = h1 + (tl >> 2), ww = w1 + (tl & 3);
        size_t gbase = (size_t)((n << 10) + hh * 32 + ww) * 1536 + head * 64 + f * 4;
        *(float4*)&sq[tl * KVSTRIDE + f * 4] = *(const float4*)&g_qkv[gbase];
    }
    __syncthreads();

    // ---- logits: 16 tokens x 49 window positions ----
    for (int it = tid; it < 16 * WIN; it += 256) {
        int tl = it / WIN, wp = it - tl * WIN;
        int hh = h1 + (tl >> 2), ww = w1 + (tl & 3);
        int dh0 = min(max(hh - 3, 0), HH - KSZ) - h0min;
        int dw0 = min(max(ww - 3, 0), WWID - KSZ) - w0min;
        int kr = wp / KSZ, kc = wp - kr * KSZ;
        const float4* kv = (const float4*)&sk[((dh0 + kr) * span_w + dw0 + kc) * KVSTRIDE];
        const float4* qv = (const float4*)&sq[tl * KVSTRIDE];
        float acc = 0.0f;
#pragma unroll
        for (int i = 0; i < 16; i++) {
            float4 a = kv[i], b = qv[i];
            acc += a.x * b.x + a.y * b.y + a.z * b.z + a.w * b.w;
        }
        sl[tl * 52 + wp] = acc;
    }
    __syncthreads();

    // ---- softmax per token (16 threads) ----
    if (tid < 16) {
        float mx = -1e30f;
#pragma unroll
        for (int j = 0; j < WIN; j++) mx = fmaxf(mx, sl[tid * 52 + j]);
        float den = 0.0f;
#pragma unroll
        for (int j = 0; j < WIN; j++) {
            float e = __expf(sl[tid * 52 + j] - mx);
            sl[tid * 52 + j] = e;
            den += e;
        }
        pinv[tid] = 1.0f / den;
    }
    __syncthreads();

    // ---- output: 16 tokens x 64 channels ----
    for (int idxo = tid; idxo < 16 * 64; idxo += 256) {
        int tl = idxo >> 6, e = idxo & 63;
        int hh = h1 + (tl >> 2), ww = w1 + (tl & 3);
        int dh0 = min(max(hh - 3, 0), HH - KSZ) - h0min;
        int dw0 = min(max(ww - 3, 0), WWID - KSZ) - w0min;
        float acc = 0.0f;
#pragma unroll
        for (int kr = 0; kr < KSZ; kr++) {
            int base = (dh0 + kr) * span_w + dw0;
#pragma unroll
            for (int kc = 0; kc < KSZ; kc++) {
                acc += sl[tl * 52 + kr * KSZ + kc] * sv[(base + kc) * KVSTRIDE + e];
            }
        }
        g_o[(size_t)((n << 10) + hh * 32 + ww) * 512 + head * 64 + e] = acc * pinv[tl];
    }
}

// ---------------- launch ------------------------------------------------------
extern "C" void kernel_launch(void* const* d_in, const int* in_sizes, int n_in,
                              void* d_out, int out_size) {
    const float* x      = (const float*)d_in[0];
    const float* pos    = (const float*)d_in[1];
    const float* cond   = (const float*)d_in[2];
    const float* norm_w = (const float*)d_in[3];
    const float* qkv_w  = (const float*)d_in[4];
    const float* scale  = (const float*)d_in[5];
    const float* out_w  = (const float*)d_in[6];
    float* out = (float*)d_out;

    float *p_xn, *p_qkv, *p_o;
    cudaGetSymbolAddress((void**)&p_xn,  g_xn);
    cudaGetSymbolAddress((void**)&p_qkv, g_qkv);
    cudaGetSymbolAddress((void**)&p_o,   g_o);

    cudaFuncSetAttribute(nsab_mma_gemm<0>,
                         cudaFuncAttributeMaxDynamicSharedMemorySize, GEMM_SMEM);
    cudaFuncSetAttribute(nsab_mma_gemm<1>,
                         cudaFuncAttributeMaxDynamicSharedMemorySize, GEMM_SMEM);
    cudaFuncSetAttribute(nsab_attn_kernel,
                         cudaFuncAttributeMaxDynamicSharedMemorySize, ATTN_SMEM);
    cudaFuncSetAttribute(nsab_norm_fused,
                         cudaFuncAttributeMaxDynamicSharedMemorySize, NORM_SMEM);

    nsab_s_kernel<<<2, 256>>>(cond, norm_w);
    nsab_norm_fused<<<NTOK / 32, 256, NORM_SMEM>>>(x);
    nsab_mma_gemm<0><<<dim3(3 * C_DIM / 128, NTOK / 128), 256, GEMM_SMEM>>>(
        p_xn, qkv_w, p_qkv, nullptr, NTOK, 3 * C_DIM, C_DIM);
    nsab_rope_kernel<<<NTOK, 256>>>(pos, scale);
    nsab_attn_kernel<<<dim3(64, NH, 4), 256, ATTN_SMEM>>>();
    nsab_mma_gemm<1><<<dim3(C_DIM / 128, NTOK / 128), 256, GEMM_SMEM>>>(
        p_o, out_w, out, x, NTOK, C_DIM, C_DIM);
}